// round 8
// baseline (speedup 1.0000x reference)
#include <cuda_runtime.h>
#include <math_constants.h>

#define EMBED    512
#define MAXLEN   2048
#define B2       256
#define TILE     128               // tokens per energy CTA
#define NTILES   (MAXLEN / TILE)   // 16
#define ETHREADS 512
#define EWARPS   (ETHREADS / 32)   // 16
#define PBLK     4                 // prep CTAs (coalesced layout)
#define PDW      128               // d-dims per prep CTA
#define PWARPS   16

// Folded linear: v = W^T * weight_vec, c = bias . weight_vec
__device__ float g_v[EMBED];
__device__ float g_c;
__device__ float g_energy[B2 * MAXLEN];   // 2 MB static scratch (L2-resident)

// ---------------------------------------------------------------------------
// Prep (coalesced, one phase): 4 CTAs x 512 threads.
// CTA blk owns d in [128*blk, 128*blk+128). Warp w accumulates rows
// e = w, w+16, ..., w+496; lane l owns float4 d0+4l. Every warp LDG is 32
// consecutive float4 (4 cache lines) -> fully coalesced. Warp partials are
// combined through smem. CTA 0 also computes c = bias . wv.
// ---------------------------------------------------------------------------
__global__ __launch_bounds__(EMBED)
void prep_kernel(const float* __restrict__ W,
                 const float* __restrict__ bias,
                 const float* __restrict__ wv) {
    __shared__ float  swv[EMBED];
    __shared__ float4 sp[PWARPS][PDW / 4];   // 16 x 32 float4 = 8 KB
    __shared__ float  sc[PWARPS];

    const int t    = threadIdx.x;
    const int warp = t >> 5;
    const int lane = t & 31;
    const int d0   = blockIdx.x * PDW;

    swv[t] = wv[t];
    __syncthreads();

    // accumulate 32 rows per warp, coalesced float4 loads
    float4 acc = make_float4(0.f, 0.f, 0.f, 0.f);
    const float* __restrict__ Wbase = W + d0 + 4 * lane;
    #pragma unroll 8
    for (int e = warp; e < EMBED; e += PWARPS) {
        const float  we = swv[e];
        const float4 w4 = *(const float4*)(Wbase + (size_t)e * EMBED);
        acc.x += w4.x * we; acc.y += w4.y * we;
        acc.z += w4.z * we; acc.w += w4.w * we;
    }
    sp[warp][lane] = acc;

    // CTA 0: bias dot partials
    if (blockIdx.x == 0) {
        float cpart = bias[t] * swv[t];
        #pragma unroll
        for (int off = 16; off > 0; off >>= 1)
            cpart += __shfl_xor_sync(0xffffffffu, cpart, off);
        if (lane == 0) sc[warp] = cpart;
    }
    __syncthreads();

    // combine: threads 0..31 each own one float4 of the d-slice
    if (t < PDW / 4) {
        float4 s = make_float4(0.f, 0.f, 0.f, 0.f);
        #pragma unroll
        for (int wdx = 0; wdx < PWARPS; ++wdx) {
            float4 p = sp[wdx][t];
            s.x += p.x; s.y += p.y; s.z += p.z; s.w += p.w;
        }
        ((float4*)(g_v + d0))[t] = s;
    }
    if (blockIdx.x == 0 && t == EMBED - 1) {
        float s = 0.0f;
        #pragma unroll
        for (int wdx = 0; wdx < PWARPS; ++wdx) s += sc[wdx];
        g_c = s;
    }
#if __CUDA_ARCH__ >= 900
    cudaTriggerProgrammaticLaunchCompletion();
#endif
}

// ---------------------------------------------------------------------------
// Energies: grid (NTILES, B2). PDL secondary: prologue + first-iteration
// q-loads run before cudaGridDependencySynchronize(); only the v-read waits
// on prep. No smem; v comes from L2-broadcast g_v reads.
// ---------------------------------------------------------------------------
__global__ __launch_bounds__(ETHREADS)
void energy_kernel(const float* __restrict__ q,
                   const int*   __restrict__ lens) {
    const int b   = blockIdx.y;
    const int len = __ldg(lens + b);
    const int l0  = blockIdx.x * TILE;
    if (l0 >= len) return;                // empty tile: zero DRAM traffic

    const int tid  = threadIdx.x;
    const int warp = tid >> 5;
    const int lane = tid & 31;

    const float4* __restrict__ qrow =
        (const float4*)(q + (size_t)b * MAXLEN * EMBED);
    const int end = min(l0 + TILE, len);

    // ---- prefetch first pair of tokens (independent of prep's output) ----
    const int l  = l0 + warp;
    const int lB = l + EWARPS;
    const bool hasA = (l  < end);
    const bool hasB = (lB < end);
    float4 a0[4], a1[4];
    if (hasA) {
        const float4* __restrict__ qp = qrow + (size_t)l * (EMBED / 4);
        #pragma unroll
        for (int k = 0; k < 4; ++k) a0[k] = __ldcs(qp + lane + 32 * k);
    }
    if (hasB) {
        const float4* __restrict__ qp = qrow + (size_t)lB * (EMBED / 4);
        #pragma unroll
        for (int k = 0; k < 4; ++k) a1[k] = __ldcs(qp + lane + 32 * k);
    }

#if __CUDA_ARCH__ >= 900
    cudaGridDependencySynchronize();      // wait for prep results
#endif

    float4 vv[4];
    const float4* __restrict__ gv4 = (const float4*)g_v;
    #pragma unroll
    for (int k = 0; k < 4; ++k) vv[k] = gv4[lane + 32 * k];
    const float c = g_c;

    float* __restrict__ erow = g_energy + (size_t)b * MAXLEN;

    // ---- first (prefetched) iteration ----
    {
        float s0 = 0.0f, s1 = 0.0f;
        if (hasA) {
            #pragma unroll
            for (int k = 0; k < 4; ++k)
                s0 += a0[k].x * vv[k].x + a0[k].y * vv[k].y
                    + a0[k].z * vv[k].z + a0[k].w * vv[k].w;
        }
        if (hasB) {
            #pragma unroll
            for (int k = 0; k < 4; ++k)
                s1 += a1[k].x * vv[k].x + a1[k].y * vv[k].y
                    + a1[k].z * vv[k].z + a1[k].w * vv[k].w;
        }
        #pragma unroll
        for (int off = 16; off > 0; off >>= 1) {
            s0 += __shfl_xor_sync(0xffffffffu, s0, off);
            s1 += __shfl_xor_sync(0xffffffffu, s1, off);
        }
        if (lane == 0) {
            if (hasA) erow[l]  = s0 + c;
            if (hasB) erow[lB] = s1 + c;
        }
    }

    // ---- remaining iterations ----
    for (int ll = l + 2 * EWARPS; ll < end; ll += 2 * EWARPS) {
        const int  ll2  = ll + EWARPS;
        const bool has2 = (ll2 < end);
        const float4* __restrict__ qp0 = qrow + (size_t)ll  * (EMBED / 4);
        const float4* __restrict__ qp1 = qrow + (size_t)ll2 * (EMBED / 4);

        float4 b0[4], b1[4];
        #pragma unroll
        for (int k = 0; k < 4; ++k) b0[k] = __ldcs(qp0 + lane + 32 * k);
        if (has2) {
            #pragma unroll
            for (int k = 0; k < 4; ++k) b1[k] = __ldcs(qp1 + lane + 32 * k);
        }

        float s0 = 0.0f, s1 = 0.0f;
        #pragma unroll
        for (int k = 0; k < 4; ++k)
            s0 += b0[k].x * vv[k].x + b0[k].y * vv[k].y
                + b0[k].z * vv[k].z + b0[k].w * vv[k].w;
        if (has2) {
            #pragma unroll
            for (int k = 0; k < 4; ++k)
                s1 += b1[k].x * vv[k].x + b1[k].y * vv[k].y
                    + b1[k].z * vv[k].z + b1[k].w * vv[k].w;
        }

        #pragma unroll
        for (int off = 16; off > 0; off >>= 1) {
            s0 += __shfl_xor_sync(0xffffffffu, s0, off);
            s1 += __shfl_xor_sync(0xffffffffu, s1, off);
        }
        if (lane == 0) {
            erow[ll] = s0 + c;
            if (has2) erow[ll2] = s1 + c;
        }
    }
}

// ---------------------------------------------------------------------------
// Softmax: one CTA (512 threads) per row, single pass, registers only.
// PDL secondary behind energy_kernel.
// ---------------------------------------------------------------------------
#define STHREADS 512
#define SWARPS   (STHREADS / 32)   // 16
__global__ __launch_bounds__(STHREADS)
void softmax_kernel(const int* __restrict__ lens,
                    float*     __restrict__ out) {
    __shared__ float sred[SWARPS];

    const int b    = blockIdx.x;
    const int len  = __ldg(lens + b);
    const int tid  = threadIdx.x;
    const int warp = tid >> 5;
    const int lane = tid & 31;
    const int base = tid * 4;

#if __CUDA_ARCH__ >= 900
    cudaGridDependencySynchronize();      // wait for energy results
#endif

    const float4* __restrict__ erow4 =
        (const float4*)(g_energy + (size_t)b * MAXLEN);

    float4 e = erow4[tid];
    const bool v0 = (base + 0 < len), v1 = (base + 1 < len),
               v2 = (base + 2 < len), v3 = (base + 3 < len);

    float m = -CUDART_INF_F;
    if (v0) m = fmaxf(m, e.x);
    if (v1) m = fmaxf(m, e.y);
    if (v2) m = fmaxf(m, e.z);
    if (v3) m = fmaxf(m, e.w);
    #pragma unroll
    for (int off = 16; off > 0; off >>= 1)
        m = fmaxf(m, __shfl_xor_sync(0xffffffffu, m, off));
    if (lane == 0) sred[warp] = m;
    __syncthreads();
    {
        float mm = sred[lane & (SWARPS - 1)];
        #pragma unroll
        for (int off = 8; off > 0; off >>= 1)
            mm = fmaxf(mm, __shfl_xor_sync(0xffffffffu, mm, off));
        m = mm;
    }
    __syncthreads();

    e.x = v0 ? __expf(e.x - m) : 0.0f;
    e.y = v1 ? __expf(e.y - m) : 0.0f;
    e.z = v2 ? __expf(e.z - m) : 0.0f;
    e.w = v3 ? __expf(e.w - m) : 0.0f;
    float ssum = e.x + e.y + e.z + e.w;
    #pragma unroll
    for (int off = 16; off > 0; off >>= 1)
        ssum += __shfl_xor_sync(0xffffffffu, ssum, off);
    if (lane == 0) sred[warp] = ssum;
    __syncthreads();
    {
        float t = sred[lane & (SWARPS - 1)];
        #pragma unroll
        for (int off = 8; off > 0; off >>= 1)
            t += __shfl_xor_sync(0xffffffffu, t, off);
        ssum = t;
    }
    const float inv = 1.0f / ssum;

    float4 o;
    o.x = e.x * inv; o.y = e.y * inv; o.z = e.z * inv; o.w = e.w * inv;
    ((float4*)(out + (size_t)b * MAXLEN))[tid] = o;
}

// ---------------------------------------------------------------------------
// Launch with PDL chaining: prep -> energy -> softmax.
// inputs: questions, questions_lens, lin_w, lin_b, weight_vec
// ---------------------------------------------------------------------------
extern "C" void kernel_launch(void* const* d_in, const int* in_sizes, int n_in,
                              void* d_out, int out_size) {
    const float* questions = (const float*)d_in[0];
    const int*   lens      = (const int*)  d_in[1];
    const float* lin_w     = (const float*)d_in[2];
    const float* lin_b     = (const float*)d_in[3];
    const float* wv        = (const float*)d_in[4];
    float* out = (float*)d_out;

    prep_kernel<<<PBLK, EMBED>>>(lin_w, lin_b, wv);

    cudaLaunchAttribute pdl[1];
    pdl[0].id = cudaLaunchAttributeProgrammaticStreamSerialization;
    pdl[0].val.programmaticStreamSerializationAllowed = 1;

    {
        cudaLaunchConfig_t cfg = {};
        cfg.gridDim  = dim3(NTILES, B2, 1);
        cfg.blockDim = dim3(ETHREADS, 1, 1);
        cfg.stream   = 0;
        cfg.attrs    = pdl;
        cfg.numAttrs = 1;
        cudaLaunchKernelEx(&cfg, energy_kernel, questions, lens);
    }
    {
        cudaLaunchConfig_t cfg = {};
        cfg.gridDim  = dim3(B2, 1, 1);
        cfg.blockDim = dim3(STHREADS, 1, 1);
        cfg.stream   = 0;
        cfg.attrs    = pdl;
        cfg.numAttrs = 1;
        cudaLaunchKernelEx(&cfg, softmax_kernel, lens, out);
    }
}

// round 9
// speedup vs baseline: 1.0414x; 1.0414x over previous
#include <cuda_runtime.h>
#include <math_constants.h>

#define EMBED    512
#define MAXLEN   2048
#define B2       256
#define TILE     64                // tokens per energy CTA
#define NTILES   (MAXLEN / TILE)   // 32
#define ETHREADS 512
#define EWARPS   (ETHREADS / 32)   // 16
#define PBLK     64                // prep CTAs
#define PD       (EMBED / PBLK)    // 8 output dims per prep CTA

// Folded linear: v = W^T * weight_vec, c = bias . weight_vec
__device__ float g_v[EMBED];
__device__ float g_c;
__device__ float g_energy[B2 * MAXLEN];   // 2 MB static scratch (L2-resident)

// ---------------------------------------------------------------------------
// Prep (single pass, 64 CTAs — latency spread across 64 SMs; R6 layout).
// CTA blk owns output dims d0..d0+7 and reduces over ALL e in-CTA:
// thread t handles e=t, warp-shuffle + smem tree reduces the 8 components.
// CTA 0 also computes c = bias . wv.
// ---------------------------------------------------------------------------
__global__ __launch_bounds__(EMBED)
void prep_kernel(const float* __restrict__ W,
                 const float* __restrict__ bias,
                 const float* __restrict__ wv) {
    __shared__ float sp[16][PD];     // per-warp partials (16 warps)
    __shared__ float sc[16];         // per-warp partials for c (CTA 0)

    const int t    = threadIdx.x;    // e index
    const int warp = t >> 5;
    const int lane = t & 31;
    const int d0   = blockIdx.x * PD;

    const float w = wv[t];
    const float4* __restrict__ Wp =
        (const float4*)(W + (size_t)t * EMBED + d0);
    float4 w0 = Wp[0];
    float4 w1 = Wp[1];

    float a[PD];
    a[0] = w0.x * w; a[1] = w0.y * w; a[2] = w0.z * w; a[3] = w0.w * w;
    a[4] = w1.x * w; a[5] = w1.y * w; a[6] = w1.z * w; a[7] = w1.w * w;

    #pragma unroll
    for (int off = 16; off > 0; off >>= 1) {
        #pragma unroll
        for (int j = 0; j < PD; ++j)
            a[j] += __shfl_xor_sync(0xffffffffu, a[j], off);
    }
    if (lane == 0) {
        #pragma unroll
        for (int j = 0; j < PD; ++j) sp[warp][j] = a[j];
    }

    float cpart = 0.0f;
    if (blockIdx.x == 0) {
        cpart = bias[t] * w;
        #pragma unroll
        for (int off = 16; off > 0; off >>= 1)
            cpart += __shfl_xor_sync(0xffffffffu, cpart, off);
        if (lane == 0) sc[warp] = cpart;
    }
    __syncthreads();

    if (t < PD) {
        float s = 0.0f;
        #pragma unroll
        for (int wdx = 0; wdx < 16; ++wdx) s += sp[wdx][t];
        g_v[d0 + t] = s;
    }
    if (blockIdx.x == 0 && t == EMBED - 1) {
        float s = 0.0f;
        #pragma unroll
        for (int wdx = 0; wdx < 16; ++wdx) s += sc[wdx];
        g_c = s;
    }
#if __CUDA_ARCH__ >= 900
    cudaTriggerProgrammaticLaunchCompletion();
#endif
}

// ---------------------------------------------------------------------------
// Energies: grid (NTILES, B2), 64-token tiles for fine ragged load balance.
// PDL secondary: prologue + first-iteration q-loads run before
// cudaGridDependencySynchronize(); only the v-read waits on prep.
// ---------------------------------------------------------------------------
__global__ __launch_bounds__(ETHREADS)
void energy_kernel(const float* __restrict__ q,
                   const int*   __restrict__ lens) {
    const int b   = blockIdx.y;
    const int len = __ldg(lens + b);
    const int l0  = blockIdx.x * TILE;
    if (l0 >= len) return;                // empty tile: zero DRAM traffic

    const int tid  = threadIdx.x;
    const int warp = tid >> 5;
    const int lane = tid & 31;

    const float4* __restrict__ qrow =
        (const float4*)(q + (size_t)b * MAXLEN * EMBED);
    const int end = min(l0 + TILE, len);

    // ---- prefetch first pair of tokens (independent of prep's output) ----
    const int l  = l0 + warp;
    const int lB = l + EWARPS;
    const bool hasA = (l  < end);
    const bool hasB = (lB < end);
    float4 a0[4], a1[4];
    if (hasA) {
        const float4* __restrict__ qp = qrow + (size_t)l * (EMBED / 4);
        #pragma unroll
        for (int k = 0; k < 4; ++k) a0[k] = __ldcs(qp + lane + 32 * k);
    }
    if (hasB) {
        const float4* __restrict__ qp = qrow + (size_t)lB * (EMBED / 4);
        #pragma unroll
        for (int k = 0; k < 4; ++k) a1[k] = __ldcs(qp + lane + 32 * k);
    }

#if __CUDA_ARCH__ >= 900
    cudaGridDependencySynchronize();      // wait for prep results
#endif

    float4 vv[4];
    const float4* __restrict__ gv4 = (const float4*)g_v;
    #pragma unroll
    for (int k = 0; k < 4; ++k) vv[k] = gv4[lane + 32 * k];
    const float c = g_c;

    float* __restrict__ erow = g_energy + (size_t)b * MAXLEN;

    // ---- first (prefetched) iteration ----
    {
        float s0 = 0.0f, s1 = 0.0f;
        if (hasA) {
            #pragma unroll
            for (int k = 0; k < 4; ++k)
                s0 += a0[k].x * vv[k].x + a0[k].y * vv[k].y
                    + a0[k].z * vv[k].z + a0[k].w * vv[k].w;
        }
        if (hasB) {
            #pragma unroll
            for (int k = 0; k < 4; ++k)
                s1 += a1[k].x * vv[k].x + a1[k].y * vv[k].y
                    + a1[k].z * vv[k].z + a1[k].w * vv[k].w;
        }
        #pragma unroll
        for (int off = 16; off > 0; off >>= 1) {
            s0 += __shfl_xor_sync(0xffffffffu, s0, off);
            s1 += __shfl_xor_sync(0xffffffffu, s1, off);
        }
        if (lane == 0) {
            if (hasA) erow[l]  = s0 + c;
            if (hasB) erow[lB] = s1 + c;
        }
    }

    // ---- remaining iterations (only for partial tiles beyond 2*EWARPS) ----
    for (int ll = l + 2 * EWARPS; ll < end; ll += 2 * EWARPS) {
        const int  ll2  = ll + EWARPS;
        const bool has2 = (ll2 < end);
        const float4* __restrict__ qp0 = qrow + (size_t)ll  * (EMBED / 4);
        const float4* __restrict__ qp1 = qrow + (size_t)ll2 * (EMBED / 4);

        float4 b0[4], b1[4];
        #pragma unroll
        for (int k = 0; k < 4; ++k) b0[k] = __ldcs(qp0 + lane + 32 * k);
        if (has2) {
            #pragma unroll
            for (int k = 0; k < 4; ++k) b1[k] = __ldcs(qp1 + lane + 32 * k);
        }

        float s0 = 0.0f, s1 = 0.0f;
        #pragma unroll
        for (int k = 0; k < 4; ++k)
            s0 += b0[k].x * vv[k].x + b0[k].y * vv[k].y
                + b0[k].z * vv[k].z + b0[k].w * vv[k].w;
        if (has2) {
            #pragma unroll
            for (int k = 0; k < 4; ++k)
                s1 += b1[k].x * vv[k].x + b1[k].y * vv[k].y
                    + b1[k].z * vv[k].z + b1[k].w * vv[k].w;
        }

        #pragma unroll
        for (int off = 16; off > 0; off >>= 1) {
            s0 += __shfl_xor_sync(0xffffffffu, s0, off);
            s1 += __shfl_xor_sync(0xffffffffu, s1, off);
        }
        if (lane == 0) {
            erow[ll] = s0 + c;
            if (has2) erow[ll2] = s1 + c;
        }
    }
}

// ---------------------------------------------------------------------------
// Softmax: one CTA (512 threads) per row, single pass, registers only.
// PDL secondary behind energy_kernel.
// ---------------------------------------------------------------------------
#define STHREADS 512
#define SWARPS   (STHREADS / 32)   // 16
__global__ __launch_bounds__(STHREADS)
void softmax_kernel(const int* __restrict__ lens,
                    float*     __restrict__ out) {
    __shared__ float sred[SWARPS];

    const int b    = blockIdx.x;
    const int tid  = threadIdx.x;
    const int warp = tid >> 5;
    const int lane = tid & 31;
    const int base = tid * 4;
    const int len  = __ldg(lens + b);     // independent of energy results

#if __CUDA_ARCH__ >= 900
    cudaGridDependencySynchronize();      // wait for energy results
#endif

    const float4* __restrict__ erow4 =
        (const float4*)(g_energy + (size_t)b * MAXLEN);

    float4 e = erow4[tid];
    const bool v0 = (base + 0 < len), v1 = (base + 1 < len),
               v2 = (base + 2 < len), v3 = (base + 3 < len);

    float m = -CUDART_INF_F;
    if (v0) m = fmaxf(m, e.x);
    if (v1) m = fmaxf(m, e.y);
    if (v2) m = fmaxf(m, e.z);
    if (v3) m = fmaxf(m, e.w);
    #pragma unroll
    for (int off = 16; off > 0; off >>= 1)
        m = fmaxf(m, __shfl_xor_sync(0xffffffffu, m, off));
    if (lane == 0) sred[warp] = m;
    __syncthreads();
    {
        float mm = sred[lane & (SWARPS - 1)];
        #pragma unroll
        for (int off = 8; off > 0; off >>= 1)
            mm = fmaxf(mm, __shfl_xor_sync(0xffffffffu, mm, off));
        m = mm;
    }
    __syncthreads();

    e.x = v0 ? __expf(e.x - m) : 0.0f;
    e.y = v1 ? __expf(e.y - m) : 0.0f;
    e.z = v2 ? __expf(e.z - m) : 0.0f;
    e.w = v3 ? __expf(e.w - m) : 0.0f;
    float ssum = e.x + e.y + e.z + e.w;
    #pragma unroll
    for (int off = 16; off > 0; off >>= 1)
        ssum += __shfl_xor_sync(0xffffffffu, ssum, off);
    if (lane == 0) sred[warp] = ssum;
    __syncthreads();
    {
        float t = sred[lane & (SWARPS - 1)];
        #pragma unroll
        for (int off = 8; off > 0; off >>= 1)
            t += __shfl_xor_sync(0xffffffffu, t, off);
        ssum = t;
    }
    const float inv = 1.0f / ssum;

    float4 o;
    o.x = e.x * inv; o.y = e.y * inv; o.z = e.z * inv; o.w = e.w * inv;
    ((float4*)(out + (size_t)b * MAXLEN))[tid] = o;
}

// ---------------------------------------------------------------------------
// Launch with PDL chaining: prep -> energy -> softmax.
// inputs: questions, questions_lens, lin_w, lin_b, weight_vec
// ---------------------------------------------------------------------------
extern "C" void kernel_launch(void* const* d_in, const int* in_sizes, int n_in,
                              void* d_out, int out_size) {
    const float* questions = (const float*)d_in[0];
    const int*   lens      = (const int*)  d_in[1];
    const float* lin_w     = (const float*)d_in[2];
    const float* lin_b     = (const float*)d_in[3];
    const float* wv        = (const float*)d_in[4];
    float* out = (float*)d_out;

    prep_kernel<<<PBLK, EMBED>>>(lin_w, lin_b, wv);

    cudaLaunchAttribute pdl[1];
    pdl[0].id = cudaLaunchAttributeProgrammaticStreamSerialization;
    pdl[0].val.programmaticStreamSerializationAllowed = 1;

    {
        cudaLaunchConfig_t cfg = {};
        cfg.gridDim  = dim3(NTILES, B2, 1);
        cfg.blockDim = dim3(ETHREADS, 1, 1);
        cfg.stream   = 0;
        cfg.attrs    = pdl;
        cfg.numAttrs = 1;
        cudaLaunchKernelEx(&cfg, energy_kernel, questions, lens);
    }
    {
        cudaLaunchConfig_t cfg = {};
        cfg.gridDim  = dim3(B2, 1, 1);
        cfg.blockDim = dim3(STHREADS, 1, 1);
        cfg.stream   = 0;
        cfg.attrs    = pdl;
        cfg.numAttrs = 1;
        cudaLaunchKernelEx(&cfg, softmax_kernel, lens, out);
    }
}